// round 5
// baseline (speedup 1.0000x reference)
#include <cuda_runtime.h>
#include <cuda_bf16.h>
#include <cstdint>

#define BB 8
#define LXX 2048
#define LYY 2048
#define DD 256

// ---------------- global scratch (no cudaMalloc allowed) ----------------
__device__ __nv_bfloat16 g_xp_h[BB * LXX * DD];
__device__ __nv_bfloat16 g_xp_l[BB * LXX * DD];
__device__ __nv_bfloat16 g_yp_h[BB * LYY * DD];
__device__ __nv_bfloat16 g_yp_l[BB * LYY * DD];
__device__ __nv_bfloat16 g_yv_h[BB * LYY * DD];
__device__ __nv_bfloat16 g_yv_l[BB * LYY * DD];
__device__ __nv_bfloat16 g_W_h[DD * DD];
__device__ __nv_bfloat16 g_W_l[DD * DD];

// ---------------- helpers (portable PTX only) ----------------
__device__ __forceinline__ uint32_t smem_u32(const void* p) {
    uint32_t a;
    asm("{ .reg .u64 t; cvta.to.shared.u64 t, %1; cvt.u32.u64 %0, t; }" : "=r"(a) : "l"(p));
    return a;
}
__device__ __forceinline__ void cpa16(uint32_t s, const void* g) {
    asm volatile("cp.async.cg.shared.global [%0], [%1], 16;" :: "r"(s), "l"(g));
}
__device__ __forceinline__ void cpa4(uint32_t s, const void* g) {
    asm volatile("cp.async.ca.shared.global [%0], [%1], 4;" :: "r"(s), "l"(g));
}
#define CP_COMMIT() asm volatile("cp.async.commit_group;" ::: "memory")
#define CP_WAIT0()  asm volatile("cp.async.wait_group 0;" ::: "memory")
#define CP_WAIT1()  asm volatile("cp.async.wait_group 1;" ::: "memory")

__device__ __forceinline__ void ldsm4(uint32_t r[4], uint32_t a) {
    asm volatile("ldmatrix.sync.aligned.m8n8.x4.shared.b16 {%0,%1,%2,%3}, [%4];"
                 : "=r"(r[0]), "=r"(r[1]), "=r"(r[2]), "=r"(r[3]) : "r"(a));
}
__device__ __forceinline__ void ldsm4t(uint32_t r[4], uint32_t a) {
    asm volatile("ldmatrix.sync.aligned.m8n8.x4.trans.shared.b16 {%0,%1,%2,%3}, [%4];"
                 : "=r"(r[0]), "=r"(r[1]), "=r"(r[2]), "=r"(r[3]) : "r"(a));
}
__device__ __forceinline__ void mma16816(float c[4], const uint32_t a[4],
                                         uint32_t b0, uint32_t b1) {
    asm volatile(
        "mma.sync.aligned.m16n8k16.row.col.f32.bf16.bf16.f32 "
        "{%0,%1,%2,%3}, {%4,%5,%6,%7}, {%8,%9}, {%0,%1,%2,%3};"
        : "+f"(c[0]), "+f"(c[1]), "+f"(c[2]), "+f"(c[3])
        : "r"(a[0]), "r"(a[1]), "r"(a[2]), "r"(a[3]), "r"(b0), "r"(b1));
}
__device__ __forceinline__ uint32_t cvt2bf(float lo, float hi) {
    uint32_t r;
    asm("cvt.rn.bf16x2.f32 %0, %1, %2;" : "=r"(r) : "f"(hi), "f"(lo));
    return r;
}
__device__ __forceinline__ float exp2p(float t) {
    t = fmaxf(t, -126.0f);
    float n = rintf(t);
    float f = t - n;
    float p = fmaf(1.5403530e-4f, f, 1.3333558e-3f);
    p = fmaf(p, f, 9.6181290e-3f);
    p = fmaf(p, f, 5.5504109e-2f);
    p = fmaf(p, f, 2.4022651e-1f);
    p = fmaf(p, f, 6.9314718e-1f);
    p = fmaf(p, f, 1.0f);
    return p * __int_as_float(((int)n + 127) << 23);
}
#define L2E 1.4426950408889634f

// ---------------------------------------------------------------------------
// Tiny splits: W -> g_W_{h,l},  y -> g_yv_{h,l}
// ---------------------------------------------------------------------------
__global__ __launch_bounds__(256)
void split_W(const float* __restrict__ W)
{
    size_t i = ((size_t)blockIdx.x * 256 + threadIdx.x) * 4;
    float4 v = *(const float4*)(W + i);
    float vv[4] = {v.x, v.y, v.z, v.w};
    __nv_bfloat16 h[4], l[4];
#pragma unroll
    for (int k = 0; k < 4; k++) {
        h[k] = __float2bfloat16_rn(vv[k]);
        l[k] = __float2bfloat16_rn(vv[k] - __bfloat162float(h[k]));
    }
    *(uint2*)&g_W_h[i] = *(uint2*)h;
    *(uint2*)&g_W_l[i] = *(uint2*)l;
}
__global__ __launch_bounds__(256)
void split_y(const float* __restrict__ y)
{
    size_t i = ((size_t)blockIdx.x * 256 + threadIdx.x) * 4;
    float4 v = *(const float4*)(y + i);
    float vv[4] = {v.x, v.y, v.z, v.w};
    __nv_bfloat16 h[4], l[4];
#pragma unroll
    for (int k = 0; k < 4; k++) {
        h[k] = __float2bfloat16_rn(vv[k]);
        l[k] = __float2bfloat16_rn(vv[k] - __bfloat162float(h[k]));
    }
    *(uint2*)&g_yv_h[i] = *(uint2*)h;
    *(uint2*)&g_yv_l[i] = *(uint2*)l;
}

// ---------------------------------------------------------------------------
// Tensor-core projection: C = relu(A @ W^T + b) -> bf16 h/l splits.
// CTA = 128 rows x 256 cols, 8 warps x 16 rows. k chunks of 32, double-buffered.
// Virtual row space: rows [0,16384) = x -> g_xp, [16384,32768) = y -> g_yp.
// ---------------------------------------------------------------------------
#define PA32 0            // fp32 A stage: 128 x 144B, x2 stages (36864)
#define PAH  36864        // A hi bf16: 128 x 80B
#define PAL  47104        // A lo bf16
#define PW   57344        // W stages: per stage 40960 (Wh 256x80, Wl +20480)
#define PTOT (57344 + 2 * 40960)

__global__ __launch_bounds__(256, 1)
void proj_mma_kernel(const float* __restrict__ x,
                     const float* __restrict__ y,
                     const float* __restrict__ bias)
{
    extern __shared__ char smc[];
    const uint32_t sa = smem_u32(smc);
    const int tid  = threadIdx.x;
    const int w    = tid >> 5;
    const int lane = tid & 31;
    const int lr   = lane >> 2;
    const int tig  = lane & 3;
    const int rw   = w * 16;
    const int bid  = blockIdx.x;

    const float* Asrc;
    __nv_bfloat16 *Ch, *Cl;
    int row0;
    if (bid < 128) { Asrc = x; row0 = bid * 128;        Ch = g_xp_h; Cl = g_xp_l; }
    else           { Asrc = y; row0 = (bid - 128) * 128; Ch = g_yp_h; Cl = g_yp_l; }

    const int lrow = tid >> 1, lhalf = tid & 1;

    // prefetch stage s for k-chunk kc
    auto prefetch = [&](int s, int kc) {
        // A fp32: 128 rows x 32 floats
        const float* g = Asrc + (size_t)(row0 + lrow) * DD + kc * 32 + lhalf * 16;
        uint32_t sA = sa + PA32 + s * 18432 + lrow * 144 + lhalf * 64;
#pragma unroll
        for (int i = 0; i < 4; i++) cpa16(sA + i * 16, g + i * 4);
        // W h/l: 256 rows x 32 bf16
        const __nv_bfloat16* gh = g_W_h + (size_t)tid * DD + kc * 32;
        const __nv_bfloat16* gl = g_W_l + (size_t)tid * DD + kc * 32;
        uint32_t sW = sa + PW + s * 40960 + tid * 80;
#pragma unroll
        for (int i = 0; i < 4; i++) {
            cpa16(sW + i * 16, gh + i * 8);
            cpa16(sW + 20480 + i * 16, gl + i * 8);
        }
    };

    float O[32][4];
#pragma unroll
    for (int i = 0; i < 32; i++) { O[i][0] = O[i][1] = O[i][2] = O[i][3] = 0.f; }

    const uint32_t aAbase = sa + PAH + (rw + (lane & 7) + ((lane >> 3) & 1) * 8) * 80
                          + (lane >> 4) * 16;
    const uint32_t aBbase = sa + PW + ((lane & 7) + ((lane < 16) ? 0 : 8)) * 80
                          + ((lane >> 3) & 1) * 16;

    prefetch(0, 0);
    CP_COMMIT();

#pragma unroll 1
    for (int kc = 0; kc < 8; kc++) {
        const int s = kc & 1;
        if (kc < 7) { prefetch(s ^ 1, kc + 1); CP_COMMIT(); CP_WAIT1(); }
        else        { CP_WAIT0(); }
        __syncthreads();

        // convert A fp32 stage -> bf16 h/l (single buffer)
        {
            uint32_t base = (uint32_t)(PA32 + s * 18432 + lrow * 144 + lhalf * 64);
            float4 f[4];
#pragma unroll
            for (int i = 0; i < 4; i++) f[i] = *(const float4*)(smc + base + i * 16);
            uint32_t hh[8], ll[8];
#pragma unroll
            for (int i = 0; i < 8; i++) {
                float v0 = ((const float*)f)[2 * i], v1 = ((const float*)f)[2 * i + 1];
                uint32_t h = cvt2bf(v0, v1);
                hh[i] = h;
                float r0 = v0 - __uint_as_float(h << 16);
                float r1 = v1 - __uint_as_float(h & 0xffff0000u);
                ll[i] = cvt2bf(r0, r1);
            }
            uint32_t dst = (uint32_t)(lrow * 80 + lhalf * 32);
            *(uint4*)(smc + PAH + dst)      = *(uint4*)(hh);
            *(uint4*)(smc + PAH + dst + 16) = *(uint4*)(hh + 4);
            *(uint4*)(smc + PAL + dst)      = *(uint4*)(ll);
            *(uint4*)(smc + PAL + dst + 16) = *(uint4*)(ll + 4);
        }
        __syncthreads();

        // mma: 2 k16 steps x 16 n-groups x 3 passes
#pragma unroll
        for (int kk = 0; kk < 2; kk++) {
            uint32_t ah[4], al[4];
            ldsm4(ah, aAbase + kk * 32);
            ldsm4(al, aAbase + 10240 + kk * 32);
            uint32_t bB = aBbase + s * 40960 + kk * 32;
#pragma unroll 4
            for (int g = 0; g < 16; g++) {
                uint32_t bh[4], bl[4];
                ldsm4(bh, bB + g * 1280);
                ldsm4(bl, bB + 20480 + g * 1280);
                mma16816(O[2 * g],     ah, bh[0], bh[1]);
                mma16816(O[2 * g],     ah, bl[0], bl[1]);
                mma16816(O[2 * g],     al, bh[0], bh[1]);
                mma16816(O[2 * g + 1], ah, bh[2], bh[3]);
                mma16816(O[2 * g + 1], ah, bl[2], bl[3]);
                mma16816(O[2 * g + 1], al, bh[2], bh[3]);
            }
        }
        __syncthreads();
    }

    // epilogue: bias + relu + h/l split + store
    const int r0g = row0 + rw + lr;
#pragma unroll
    for (int od = 0; od < 32; od++) {
        int c = od * 8 + tig * 2;
        float b0 = __ldg(bias + c), b1 = __ldg(bias + c + 1);
#pragma unroll
        for (int half = 0; half < 2; half++) {
            float v0 = fmaxf(O[od][2 * half]     + b0, 0.f);
            float v1 = fmaxf(O[od][2 * half + 1] + b1, 0.f);
            uint32_t h = cvt2bf(v0, v1);
            float r0 = v0 - __uint_as_float(h << 16);
            float r1 = v1 - __uint_as_float(h & 0xffff0000u);
            uint32_t l = cvt2bf(r0, r1);
            size_t o = (size_t)(r0g + half * 8) * DD + c;
            *(uint32_t*)&Ch[o] = h;
            *(uint32_t*)&Cl[o] = l;
        }
    }
}

// ---------------------------------------------------------------------------
// Fused mma.sync attention. CTA = (b, 128 x-rows), 8 warps x 16 rows, D=256
// in registers. LY streamed in 16-col tiles, 2-stage cp.async double buffer.
// ---------------------------------------------------------------------------
#define SXSTR 528
#define SXH 0
#define SXL 67584
#define SB  135168          // stage base
#define STG 33920           // stage stride
#define YPL_O 8448
#define YVH_O 16896
#define YVL_O 25344
#define MK_O  33792
#define SMTOT (SB + 2 * STG)
#define NT (LYY / 16)

__global__ __launch_bounds__(256, 1)
void attn_mma_kernel(const int* __restrict__ mask, float* __restrict__ out)
{
    extern __shared__ char smc[];
    const uint32_t sa = smem_u32(smc);
    const int tid  = threadIdx.x;
    const int w    = tid >> 5;
    const int lane = tid & 31;
    const int lr   = lane >> 2;
    const int tig  = lane & 3;
    const int b    = blockIdx.y;
    const int x0   = blockIdx.x * 128;
    const int rw   = w * 16;

    // ---- Xp tile loads (h+l), 128 rows x 512B ----
    {
        int r = tid >> 1;
        const __nv_bfloat16* srch = g_xp_h + (size_t)(b * LXX + x0 + r) * DD;
        const __nv_bfloat16* srcl = g_xp_l + (size_t)(b * LXX + x0 + r) * DD;
        uint32_t dh = sa + SXH + r * SXSTR;
        uint32_t dl = sa + SXL + r * SXSTR;
#pragma unroll
        for (int i = 0; i < 16; i++) {
            int c = (tid & 1) + 2 * i;
            cpa16(dh + c * 16, srch + c * 8);
            cpa16(dl + c * 16, srcl + c * 8);
        }
    }
    CP_COMMIT();

    const int* mB = mask + (size_t)b * LYY;
    const size_t gyB = (size_t)(b * LYY) * DD;

    const int pr = tid >> 4, pc = (tid & 15) * 2;   // prefetch row / chunk pair

    auto prefetch = [&](int s, int t) {
        size_t gro = gyB + (size_t)(t * 16 + pr) * DD;
        uint32_t st = sa + SB + s * STG + pr * SXSTR;
#pragma unroll
        for (int q = 0; q < 2; q++) {
            int c = pc + q;
            cpa16(st + c * 16,         g_yp_h + gro + c * 8);
            cpa16(st + YPL_O + c * 16, g_yp_l + gro + c * 8);
            cpa16(st + YVH_O + c * 16, g_yv_h + gro + c * 8);
            cpa16(st + YVL_O + c * 16, g_yv_l + gro + c * 8);
        }
        if (tid < 16) cpa4(sa + SB + s * STG + MK_O + tid * 4, mB + t * 16 + tid);
    };

    float O[32][4];
#pragma unroll
    for (int i = 0; i < 32; i++) { O[i][0] = O[i][1] = O[i][2] = O[i][3] = 0.f; }
    float m0 = -1e30f, m1 = -1e30f, l0 = 0.f, l1 = 0.f;

    const uint32_t aA  = sa + SXH + (rw + (lane & 7) + ((lane >> 3) & 1) * 8) * SXSTR
                       + (lane >> 4) * 16;
    const uint32_t aAl = aA + (uint32_t)(SXL - SXH);
    const uint32_t aBo = ((lane & 7) + ((lane < 16) ? 0 : 8)) * SXSTR
                       + ((lane >> 3) & 1) * 16;
    const uint32_t aVo = (uint32_t)YVH_O + ((lane & 7) + ((lane >> 3) & 1) * 8) * SXSTR
                       + ((lane < 16) ? 0 : 16);

    prefetch(0, 0);
    CP_COMMIT();

#pragma unroll 1
    for (int t = 0; t < NT; t++) {
        const int s = t & 1;
        if (t < NT - 1) { prefetch(s ^ 1, t + 1); CP_COMMIT(); CP_WAIT1(); }
        else            { CP_WAIT0(); }
        __syncthreads();

        const uint32_t stB = sa + SB + s * STG;
        const int* smk = (const int*)(smc + SB + s * STG + MK_O);

        // ---- S = Xp @ Yp^T (hh + hl + lh), 16 rows x 16 cols per warp ----
        float sf[2][4];
#pragma unroll
        for (int nt = 0; nt < 2; nt++)
#pragma unroll
            for (int i = 0; i < 4; i++) sf[nt][i] = 0.f;

        const uint32_t aB  = stB + aBo;
#pragma unroll 4
        for (int kk = 0; kk < 16; kk++) {
            uint32_t ah[4], al[4], bh[4], bl[4];
            ldsm4(ah, aA  + kk * 32);
            ldsm4(al, aAl + kk * 32);
            ldsm4(bh, aB  + kk * 32);
            ldsm4(bl, aB + YPL_O + kk * 32);
            mma16816(sf[0], ah, bh[0], bh[1]);
            mma16816(sf[0], ah, bl[0], bl[1]);
            mma16816(sf[0], al, bh[0], bh[1]);
            mma16816(sf[1], ah, bh[2], bh[3]);
            mma16816(sf[1], ah, bl[2], bl[3]);
            mma16816(sf[1], al, bh[2], bh[3]);
        }

        // ---- mask + online softmax ----
        float mx0 = -1e30f, mx1 = -1e30f;
#pragma unroll
        for (int nt = 0; nt < 2; nt++) {
            int j = 8 * nt + 2 * tig;
            if (smk[j])     { sf[nt][0] = -1e30f; sf[nt][2] = -1e30f; }
            if (smk[j + 1]) { sf[nt][1] = -1e30f; sf[nt][3] = -1e30f; }
            mx0 = fmaxf(mx0, fmaxf(sf[nt][0], sf[nt][1]));
            mx1 = fmaxf(mx1, fmaxf(sf[nt][2], sf[nt][3]));
        }
        mx0 = fmaxf(mx0, __shfl_xor_sync(0xffffffffu, mx0, 1));
        mx0 = fmaxf(mx0, __shfl_xor_sync(0xffffffffu, mx0, 2));
        mx1 = fmaxf(mx1, __shfl_xor_sync(0xffffffffu, mx1, 1));
        mx1 = fmaxf(mx1, __shfl_xor_sync(0xffffffffu, mx1, 2));

        float mn0 = fmaxf(m0, mx0), mn1 = fmaxf(m1, mx1);
        float sc0 = exp2p((m0 - mn0) * L2E);
        float sc1 = exp2p((m1 - mn1) * L2E);
        m0 = mn0; m1 = mn1;

        uint32_t ph[4], pl[4];
        float rs0 = 0.f, rs1 = 0.f;
#pragma unroll
        for (int nt = 0; nt < 2; nt++) {
            float p00 = exp2p((sf[nt][0] - mn0) * L2E);
            float p01 = exp2p((sf[nt][1] - mn0) * L2E);
            float p10 = exp2p((sf[nt][2] - mn1) * L2E);
            float p11 = exp2p((sf[nt][3] - mn1) * L2E);
            rs0 += p00 + p01;
            rs1 += p10 + p11;
            uint32_t h0 = cvt2bf(p00, p01);
            uint32_t h1 = cvt2bf(p10, p11);
            ph[nt * 2]     = h0;
            ph[nt * 2 + 1] = h1;
            float r00 = p00 - __uint_as_float(h0 << 16);
            float r01 = p01 - __uint_as_float(h0 & 0xffff0000u);
            float r10 = p10 - __uint_as_float(h1 << 16);
            float r11 = p11 - __uint_as_float(h1 & 0xffff0000u);
            pl[nt * 2]     = cvt2bf(r00, r01);
            pl[nt * 2 + 1] = cvt2bf(r10, r11);
        }
        rs0 += __shfl_xor_sync(0xffffffffu, rs0, 1);
        rs0 += __shfl_xor_sync(0xffffffffu, rs0, 2);
        rs1 += __shfl_xor_sync(0xffffffffu, rs1, 1);
        rs1 += __shfl_xor_sync(0xffffffffu, rs1, 2);
        l0 = l0 * sc0 + rs0;
        l1 = l1 * sc1 + rs1;

#pragma unroll
        for (int od = 0; od < 32; od++) {
            O[od][0] *= sc0; O[od][1] *= sc0;
            O[od][2] *= sc1; O[od][3] *= sc1;
        }

        // ---- O += P @ y  (Ph.Vh + Ph.Vl + Pl.Vh) ----
        const uint32_t aV = stB + aVo;
#pragma unroll 4
        for (int dg = 0; dg < 16; dg++) {
            uint32_t vh[4], vl[4];
            ldsm4t(vh, aV + dg * 32);
            ldsm4t(vl, aV + (YVL_O - YVH_O) + dg * 32);
            mma16816(O[2 * dg],     ph, vh[0], vh[1]);
            mma16816(O[2 * dg],     ph, vl[0], vl[1]);
            mma16816(O[2 * dg],     pl, vh[0], vh[1]);
            mma16816(O[2 * dg + 1], ph, vh[2], vh[3]);
            mma16816(O[2 * dg + 1], ph, vl[2], vl[3]);
            mma16816(O[2 * dg + 1], pl, vh[2], vh[3]);
        }
        __syncthreads();
    }

    // ---- epilogue: normalize + store ----
    float inv0 = 1.0f / l0, inv1 = 1.0f / l1;
    float* o0 = out + (size_t)(b * LXX + x0 + rw + lr) * DD;
    float* o1 = o0 + 8 * DD;
#pragma unroll
    for (int od = 0; od < 32; od++) {
        int c = od * 8 + tig * 2;
        *(float2*)(o0 + c) = make_float2(O[od][0] * inv0, O[od][1] * inv0);
        *(float2*)(o1 + c) = make_float2(O[od][2] * inv1, O[od][3] * inv1);
    }
}

// ---------------------------------------------------------------------------
extern "C" void kernel_launch(void* const* d_in, const int* in_sizes, int n_in,
                              void* d_out, int out_size)
{
    const float* x    = (const float*)d_in[0];
    const float* y    = (const float*)d_in[1];
    const int* mask   = (const int*)d_in[2];
    const float* W    = (const float*)d_in[3];
    const float* bias = (const float*)d_in[4];
    float* out        = (float*)d_out;

    split_W<<<(DD * DD) / (256 * 4), 256>>>(W);
    split_y<<<(BB * LYY * DD) / (256 * 4), 256>>>(y);

    cudaFuncSetAttribute(proj_mma_kernel,
                         cudaFuncAttributeMaxDynamicSharedMemorySize, PTOT);
    proj_mma_kernel<<<256, 256, PTOT>>>(x, y, bias);

    cudaFuncSetAttribute(attn_mma_kernel,
                         cudaFuncAttributeMaxDynamicSharedMemorySize, SMTOT);
    attn_mma_kernel<<<dim3(LXX / 128, BB), 256, SMTOT>>>(mask, out);
}

// round 6
// speedup vs baseline: 2.3992x; 2.3992x over previous
#include <cuda_runtime.h>
#include <cuda_bf16.h>
#include <cstdint>

#define BB 8
#define LXX 2048
#define LYY 2048
#define DD 256

// ---------------- global scratch (no cudaMalloc allowed) ----------------
__device__ __nv_bfloat16 g_xp_h[BB * LXX * DD];
__device__ __nv_bfloat16 g_xp_l[BB * LXX * DD];
__device__ __nv_bfloat16 g_yp_h[BB * LYY * DD];
__device__ __nv_bfloat16 g_yp_l[BB * LYY * DD];
__device__ __nv_bfloat16 g_yv_h[BB * LYY * DD];   // raw y, bf16 hi
__device__ __nv_bfloat16 g_yv_l[BB * LYY * DD];   // raw y, bf16 lo

// ---------------- helpers (portable PTX only: sm_80-era) ----------------
__device__ __forceinline__ uint32_t smem_u32(const void* p) {
    uint32_t a;
    asm("{ .reg .u64 t; cvta.to.shared.u64 t, %1; cvt.u32.u64 %0, t; }" : "=r"(a) : "l"(p));
    return a;
}
__device__ __forceinline__ void cpa16(uint32_t s, const void* g) {
    asm volatile("cp.async.cg.shared.global [%0], [%1], 16;" :: "r"(s), "l"(g));
}
__device__ __forceinline__ void cpa4(uint32_t s, const void* g) {
    asm volatile("cp.async.ca.shared.global [%0], [%1], 4;" :: "r"(s), "l"(g));
}
#define CP_COMMIT() asm volatile("cp.async.commit_group;" ::: "memory")
#define CP_WAIT0()  asm volatile("cp.async.wait_group 0;" ::: "memory")
#define CP_WAIT1()  asm volatile("cp.async.wait_group 1;" ::: "memory")

__device__ __forceinline__ void ldsm4(uint32_t r[4], uint32_t a) {
    asm volatile("ldmatrix.sync.aligned.m8n8.x4.shared.b16 {%0,%1,%2,%3}, [%4];"
                 : "=r"(r[0]), "=r"(r[1]), "=r"(r[2]), "=r"(r[3]) : "r"(a));
}
__device__ __forceinline__ void ldsm4t(uint32_t r[4], uint32_t a) {
    asm volatile("ldmatrix.sync.aligned.m8n8.x4.trans.shared.b16 {%0,%1,%2,%3}, [%4];"
                 : "=r"(r[0]), "=r"(r[1]), "=r"(r[2]), "=r"(r[3]) : "r"(a));
}
__device__ __forceinline__ void mma16816(float c[4], const uint32_t a[4],
                                         uint32_t b0, uint32_t b1) {
    asm volatile(
        "mma.sync.aligned.m16n8k16.row.col.f32.bf16.bf16.f32 "
        "{%0,%1,%2,%3}, {%4,%5,%6,%7}, {%8,%9}, {%0,%1,%2,%3};"
        : "+f"(c[0]), "+f"(c[1]), "+f"(c[2]), "+f"(c[3])
        : "r"(a[0]), "r"(a[1]), "r"(a[2]), "r"(a[3]), "r"(b0), "r"(b1));
}
__device__ __forceinline__ uint32_t cvt2bf(float lo, float hi) {
    uint32_t r;
    asm("cvt.rn.bf16x2.f32 %0, %1, %2;" : "=r"(r) : "f"(hi), "f"(lo));
    return r;
}
__device__ __forceinline__ float exp2p(float t) {
    t = fmaxf(t, -126.0f);
    float n = rintf(t);
    float f = t - n;
    float p = fmaf(1.5403530e-4f, f, 1.3333558e-3f);
    p = fmaf(p, f, 9.6181290e-3f);
    p = fmaf(p, f, 5.5504109e-2f);
    p = fmaf(p, f, 2.4022651e-1f);
    p = fmaf(p, f, 6.9314718e-1f);
    p = fmaf(p, f, 1.0f);
    return p * __int_as_float(((int)n + 127) << 23);
}
#define L2E 1.4426950408889634f

// ---------------------------------------------------------------------------
// Projection (fp32 SIMT) -> bf16 hi/lo splits. C = relu(A @ W^T + b)
// ---------------------------------------------------------------------------
__global__ __launch_bounds__(256, 1)
void proj_kernel(const float* __restrict__ A,
                 const float* __restrict__ W,
                 const float* __restrict__ bias,
                 int which)
{
    __shared__ float As[16][132];
    __shared__ float Bs[16][132];

    const int tid = threadIdx.x;
    const int tx = tid & 15;
    const int ty = tid >> 4;
    const int row0 = blockIdx.y * 128;
    const int col0 = blockIdx.x * 128;

    __nv_bfloat16* __restrict__ Ch = which ? g_yp_h : g_xp_h;
    __nv_bfloat16* __restrict__ Cl = which ? g_yp_l : g_xp_l;

    float acc[8][8];
#pragma unroll
    for (int i = 0; i < 8; i++)
#pragma unroll
        for (int j = 0; j < 8; j++) acc[i][j] = 0.0f;

    for (int k0 = 0; k0 < DD; k0 += 16) {
#pragma unroll
        for (int e = 0; e < 8; e++) {
            int elem = tid + e * 256;
            int kk = elem & 15;
            int r  = elem >> 4;
            As[kk][r] = A[(size_t)(row0 + r) * DD + k0 + kk];
            Bs[kk][r] = W[(size_t)(col0 + r) * DD + k0 + kk];
        }
        __syncthreads();
#pragma unroll
        for (int kk = 0; kk < 16; kk++) {
            float4 a0 = *(const float4*)&As[kk][ty * 8];
            float4 a1 = *(const float4*)&As[kk][ty * 8 + 4];
            float4 b0 = *(const float4*)&Bs[kk][tx * 8];
            float4 b1 = *(const float4*)&Bs[kk][tx * 8 + 4];
            float a[8] = {a0.x, a0.y, a0.z, a0.w, a1.x, a1.y, a1.z, a1.w};
            float bq[8] = {b0.x, b0.y, b0.z, b0.w, b1.x, b1.y, b1.z, b1.w};
#pragma unroll
            for (int i = 0; i < 8; i++)
#pragma unroll
                for (int j = 0; j < 8; j++)
                    acc[i][j] = fmaf(a[i], bq[j], acc[i][j]);
        }
        __syncthreads();
    }

    float bv[8];
#pragma unroll
    for (int j = 0; j < 8; j++) bv[j] = bias[col0 + tx * 8 + j];

#pragma unroll
    for (int i = 0; i < 8; i++) {
        int row = row0 + ty * 8 + i;
        __nv_bfloat16 hb[8], lb[8];
#pragma unroll
        for (int j = 0; j < 8; j++) {
            float v = fmaxf(acc[i][j] + bv[j], 0.0f);
            __nv_bfloat16 h = __float2bfloat16_rn(v);
            hb[j] = h;
            lb[j] = __float2bfloat16_rn(v - __bfloat162float(h));
        }
        size_t o = (size_t)row * DD + col0 + tx * 8;
        *(uint4*)&Ch[o] = *(uint4*)hb;
        *(uint4*)&Cl[o] = *(uint4*)lb;
    }
}

// ---------------------------------------------------------------------------
// Elementwise y -> bf16 hi/lo (natural [b][tok][d] layout)
// ---------------------------------------------------------------------------
__global__ __launch_bounds__(256)
void split_y(const float* __restrict__ y)
{
    size_t i = ((size_t)blockIdx.x * 256 + threadIdx.x) * 4;
    float4 v = *(const float4*)(y + i);
    float vv[4] = {v.x, v.y, v.z, v.w};
    __nv_bfloat16 h[4], l[4];
#pragma unroll
    for (int k = 0; k < 4; k++) {
        h[k] = __float2bfloat16_rn(vv[k]);
        l[k] = __float2bfloat16_rn(vv[k] - __bfloat162float(h[k]));
    }
    *(uint2*)&g_yv_h[i] = *(uint2*)h;
    *(uint2*)&g_yv_l[i] = *(uint2*)l;
}

// ---------------------------------------------------------------------------
// Fused mma.sync attention (R4 structure, JTILE=32) + lifetime-split
// cp.async pipelining: Yp(t+1) loads overlap PV(t); yV(t+1) loads overlap
// S(t+1). Single buffers, zero extra smem.
// ---------------------------------------------------------------------------
#define SXSTR 528                       // 256 bf16 + 8 pad, bytes
#define SXH 0
#define SXL (SXH + 128 * SXSTR)
#define SBH (SXL + 128 * SXSTR)
#define SBL (SBH + 32 * SXSTR)
#define SVH (SBL + 32 * SXSTR)
#define SVL (SVH + 32 * SXSTR)
#define SMK (SVL + 32 * SXSTR)          // 32 ints
#define SMTOT (SMK + 128)
#define NT (LYY / 32)

__global__ __launch_bounds__(256, 1)
void attn_mma_kernel(const int* __restrict__ mask, float* __restrict__ out)
{
    extern __shared__ char smc[];
    const uint32_t sa = smem_u32(smc);
    const int tid  = threadIdx.x;
    const int w    = tid >> 5;
    const int lane = tid & 31;
    const int lr   = lane >> 2;          // frag row within 8
    const int tig  = lane & 3;           // frag col pair
    const int b    = blockIdx.y;
    const int x0   = blockIdx.x * 128;
    const int rw   = w * 16;

    const int* mB = mask + (size_t)b * LYY;
    const size_t gyB = (size_t)(b * LYY) * DD;
    const int pr = tid >> 3, pcb = tid & 7;     // prefetch row / chunk base

    // group A: Yp h/l + mask for tile t
    auto issueYp = [&](int t) {
        size_t gro = gyB + (size_t)(t * 32 + pr) * DD;
        uint32_t o = sa + (uint32_t)(pr * SXSTR);
#pragma unroll
        for (int i = 0; i < 4; i++) {
            int c = pcb + 8 * i;
            cpa16(o + SBH + c * 16, g_yp_h + gro + c * 8);
            cpa16(o + SBL + c * 16, g_yp_l + gro + c * 8);
        }
        if (tid < 32) cpa4(sa + SMK + tid * 4, mB + t * 32 + tid);
    };
    // group B: yV h/l for tile t
    auto issueYv = [&](int t) {
        size_t gro = gyB + (size_t)(t * 32 + pr) * DD;
        uint32_t o = sa + (uint32_t)(pr * SXSTR);
#pragma unroll
        for (int i = 0; i < 4; i++) {
            int c = pcb + 8 * i;
            cpa16(o + SVH + c * 16, g_yv_h + gro + c * 8);
            cpa16(o + SVL + c * 16, g_yv_l + gro + c * 8);
        }
    };

    // ---- prologue: X tile (group 0), Yp(0) (group 1), yV(0) (group 2) ----
    {
        int r = tid >> 1;
        const __nv_bfloat16* srch = g_xp_h + (size_t)(b * LXX + x0 + r) * DD;
        const __nv_bfloat16* srcl = g_xp_l + (size_t)(b * LXX + x0 + r) * DD;
        uint32_t dh = sa + SXH + r * SXSTR;
        uint32_t dl = sa + SXL + r * SXSTR;
#pragma unroll
        for (int i = 0; i < 16; i++) {
            int c = (tid & 1) + 2 * i;
            cpa16(dh + c * 16, srch + c * 8);
            cpa16(dl + c * 16, srcl + c * 8);
        }
    }
    CP_COMMIT();
    issueYp(0);
    CP_COMMIT();
    issueYv(0);
    CP_COMMIT();

    const int* smk = (const int*)(smc + SMK);

    float O[32][4];
#pragma unroll
    for (int i = 0; i < 32; i++) { O[i][0] = O[i][1] = O[i][2] = O[i][3] = 0.f; }
    float m0 = -1e30f, m1 = -1e30f, l0 = 0.f, l1 = 0.f;

    const uint32_t aA  = sa + SXH + (rw + (lane & 7) + ((lane >> 3) & 1) * 8) * SXSTR
                       + (lane >> 4) * 16;
    const uint32_t aAl = aA + (uint32_t)(SXL - SXH);
    const uint32_t aB  = sa + SBH + ((lane & 7) + ((lane < 16) ? 0 : 8)) * SXSTR
                       + ((lane >> 3) & 1) * 16;
    const uint32_t aBl = aB + (uint32_t)(SBL - SBH);
    const uint32_t aV  = sa + SVH + ((lane & 7) + ((lane >> 3) & 1) * 8) * SXSTR
                       + ((lane < 16) ? 0 : 16);
    const uint32_t aVl = aV + (uint32_t)(SVL - SVH);

#pragma unroll 1
    for (int t = 0; t < NT; t++) {
        // wait: X(+first iter) and Yp(t) arrived (≤1 pending = yV(t))
        CP_WAIT1();
        __syncthreads();

        // ---- S = Xp @ Yp^T (hh + hl + lh), 16 rows x 32 cols per warp ----
        float sf[4][4];
#pragma unroll
        for (int nt = 0; nt < 4; nt++)
#pragma unroll
            for (int i = 0; i < 4; i++) sf[nt][i] = 0.f;

#pragma unroll 4
        for (int kk = 0; kk < 16; kk++) {
            uint32_t ah[4], al[4], bh[4], bl[4];
            ldsm4(ah, aA  + kk * 32);
            ldsm4(al, aAl + kk * 32);
            // j 0..15
            ldsm4(bh, aB  + kk * 32);
            ldsm4(bl, aBl + kk * 32);
            mma16816(sf[0], ah, bh[0], bh[1]);
            mma16816(sf[0], ah, bl[0], bl[1]);
            mma16816(sf[0], al, bh[0], bh[1]);
            mma16816(sf[1], ah, bh[2], bh[3]);
            mma16816(sf[1], ah, bl[2], bl[3]);
            mma16816(sf[1], al, bh[2], bh[3]);
            // j 16..31
            ldsm4(bh, aB  + 16 * SXSTR + kk * 32);
            ldsm4(bl, aBl + 16 * SXSTR + kk * 32);
            mma16816(sf[2], ah, bh[0], bh[1]);
            mma16816(sf[2], ah, bl[0], bl[1]);
            mma16816(sf[2], al, bh[0], bh[1]);
            mma16816(sf[3], ah, bh[2], bh[3]);
            mma16816(sf[3], ah, bl[2], bl[3]);
            mma16816(sf[3], al, bh[2], bh[3]);
        }

        // ---- mask + online softmax (reads smk from Yp group) ----
        float mx0 = -1e30f, mx1 = -1e30f;
#pragma unroll
        for (int nt = 0; nt < 4; nt++) {
            int j = 8 * nt + 2 * tig;
            if (smk[j])     { sf[nt][0] = -1e30f; sf[nt][2] = -1e30f; }
            if (smk[j + 1]) { sf[nt][1] = -1e30f; sf[nt][3] = -1e30f; }
            mx0 = fmaxf(mx0, fmaxf(sf[nt][0], sf[nt][1]));
            mx1 = fmaxf(mx1, fmaxf(sf[nt][2], sf[nt][3]));
        }
        mx0 = fmaxf(mx0, __shfl_xor_sync(0xffffffffu, mx0, 1));
        mx0 = fmaxf(mx0, __shfl_xor_sync(0xffffffffu, mx0, 2));
        mx1 = fmaxf(mx1, __shfl_xor_sync(0xffffffffu, mx1, 1));
        mx1 = fmaxf(mx1, __shfl_xor_sync(0xffffffffu, mx1, 2));

        float mn0 = fmaxf(m0, mx0), mn1 = fmaxf(m1, mx1);
        float sc0 = exp2p((m0 - mn0) * L2E);
        float sc1 = exp2p((m1 - mn1) * L2E);
        m0 = mn0; m1 = mn1;

        uint32_t ph[8], pl[8];
        float rs0 = 0.f, rs1 = 0.f;
#pragma unroll
        for (int nt = 0; nt < 4; nt++) {
            float p00 = exp2p((sf[nt][0] - mn0) * L2E);
            float p01 = exp2p((sf[nt][1] - mn0) * L2E);
            float p10 = exp2p((sf[nt][2] - mn1) * L2E);
            float p11 = exp2p((sf[nt][3] - mn1) * L2E);
            rs0 += p00 + p01;
            rs1 += p10 + p11;
            uint32_t h0 = cvt2bf(p00, p01);
            uint32_t h1 = cvt2bf(p10, p11);
            ph[nt * 2]     = h0;
            ph[nt * 2 + 1] = h1;
            float r00 = p00 - __uint_as_float(h0 << 16);
            float r01 = p01 - __uint_as_float(h0 & 0xffff0000u);
            float r10 = p10 - __uint_as_float(h1 << 16);
            float r11 = p11 - __uint_as_float(h1 & 0xffff0000u);
            pl[nt * 2]     = cvt2bf(r00, r01);
            pl[nt * 2 + 1] = cvt2bf(r10, r11);
        }
        rs0 += __shfl_xor_sync(0xffffffffu, rs0, 1);
        rs0 += __shfl_xor_sync(0xffffffffu, rs0, 2);
        rs1 += __shfl_xor_sync(0xffffffffu, rs1, 1);
        rs1 += __shfl_xor_sync(0xffffffffu, rs1, 2);
        l0 = l0 * sc0 + rs0;
        l1 = l1 * sc1 + rs1;

        // ---- Yp & mask now dead: overlap Yp(t+1) load with PV(t) ----
        __syncthreads();
        if (t < NT - 1) issueYp(t + 1);
        CP_COMMIT();

        // O-rescale (registers only) while Yp(t+1)/yV(t) loads fly
#pragma unroll
        for (int od = 0; od < 32; od++) {
            O[od][0] *= sc0; O[od][1] *= sc0;
            O[od][2] *= sc1; O[od][3] *= sc1;
        }

        // wait for yV(t); last iter: drain everything
        if (t < NT - 1) { CP_WAIT1(); } else { CP_WAIT0(); }
        __syncthreads();

        // ---- O += P @ y  (Ph.Vh + Ph.Vl + Pl.Vh) ----
#pragma unroll
        for (int tp = 0; tp < 2; tp++) {
            const uint32_t* pA = ph + 4 * tp;
            const uint32_t* pL = pl + 4 * tp;
            uint32_t vb  = aV  + tp * 16 * SXSTR;
            uint32_t vbl = aVl + tp * 16 * SXSTR;
#pragma unroll
            for (int dg = 0; dg < 16; dg++) {
                uint32_t vh[4], vl[4];
                ldsm4t(vh, vb  + dg * 32);
                ldsm4t(vl, vbl + dg * 32);
                mma16816(O[2 * dg],     pA, vh[0], vh[1]);
                mma16816(O[2 * dg],     pA, vl[0], vl[1]);
                mma16816(O[2 * dg],     pL, vh[0], vh[1]);
                mma16816(O[2 * dg + 1], pA, vh[2], vh[3]);
                mma16816(O[2 * dg + 1], pA, vl[2], vl[3]);
                mma16816(O[2 * dg + 1], pL, vh[2], vh[3]);
            }
        }

        // ---- yV now dead: overlap yV(t+1) load with S(t+1) ----
        __syncthreads();
        if (t < NT - 1) issueYv(t + 1);
        CP_COMMIT();
    }

    // ---- epilogue: normalize + store ----
    float inv0 = 1.0f / l0, inv1 = 1.0f / l1;
    float* o0 = out + (size_t)(b * LXX + x0 + rw + lr) * DD;
    float* o1 = o0 + 8 * DD;
#pragma unroll
    for (int od = 0; od < 32; od++) {
        int c = od * 8 + tig * 2;
        *(float2*)(o0 + c) = make_float2(O[od][0] * inv0, O[od][1] * inv0);
        *(float2*)(o1 + c) = make_float2(O[od][2] * inv1, O[od][3] * inv1);
    }
}

// ---------------------------------------------------------------------------
extern "C" void kernel_launch(void* const* d_in, const int* in_sizes, int n_in,
                              void* d_out, int out_size)
{
    const float* x    = (const float*)d_in[0];
    const float* y    = (const float*)d_in[1];
    const int* mask   = (const int*)d_in[2];
    const float* W    = (const float*)d_in[3];
    const float* bias = (const float*)d_in[4];
    float* out        = (float*)d_out;

    split_y<<<(BB * LYY * DD) / (256 * 4), 256>>>(y);
    proj_kernel<<<dim3(DD / 128, (BB * LXX) / 128), 256>>>(x, W, bias, 0);
    proj_kernel<<<dim3(DD / 128, (BB * LYY) / 128), 256>>>(y, W, bias, 1);

    cudaFuncSetAttribute(attn_mma_kernel,
                         cudaFuncAttributeMaxDynamicSharedMemorySize, SMTOT);
    attn_mma_kernel<<<dim3(LXX / 128, BB), 256, SMTOT>>>(mask, out);
}